// round 1
// baseline (speedup 1.0000x reference)
#include <cuda_runtime.h>
#include <cstdint>

#define NB 2
#define NV 2048
#define NF 2048
#define IMH 384
#define IMW 384
#define TH 1024
#define TW 1024
#define EPSF 1e-8f
#define RSLICE 4

#define ZKEY_INIT 0x7F800000FFFFFFFFull

// Scratch (static device allocations; no runtime alloc)
__device__ float g_vpix[NB * NV * 3];                      // 48 KB
__device__ unsigned long long g_zkey[NB * IMH * IMW];      // 2.36 MB

// ---------------------------------------------------------------------------
// K0: init z-buffer keys
// ---------------------------------------------------------------------------
__global__ void init_kernel() {
    int i = blockIdx.x * blockDim.x + threadIdx.x;
    if (i < NB * IMH * IMW) g_zkey[i] = ZKEY_INIT;
}

// ---------------------------------------------------------------------------
// K1: vertex transform + projection   v_pix = (focal @ (v_cam.xy / z) + pp, z)
// ---------------------------------------------------------------------------
__global__ void vtx_kernel(const float* __restrict__ v,
                           const float* __restrict__ campos,
                           const float* __restrict__ camrot,
                           const float* __restrict__ focal,
                           const float* __restrict__ princpt) {
    int i = blockIdx.x * blockDim.x + threadIdx.x;
    if (i >= NB * NV) return;
    int n = i / NV;
    const float* vp = v + (size_t)i * 3;
    float dx = vp[0] - campos[n * 3 + 0];
    float dy = vp[1] - campos[n * 3 + 1];
    float dz = vp[2] - campos[n * 3 + 2];
    const float* R = camrot + n * 9;
    float cx = R[0] * dx + R[1] * dy + R[2] * dz;
    float cy = R[3] * dx + R[4] * dy + R[5] * dz;
    float cz = R[6] * dx + R[7] * dy + R[8] * dz;
    float nx = cx / cz;
    float ny = cy / cz;
    const float* Fm = focal + n * 4;
    float px = Fm[0] * nx + Fm[1] * ny + princpt[n * 2 + 0];
    float py = Fm[2] * nx + Fm[3] * ny + princpt[n * 2 + 1];
    g_vpix[i * 3 + 0] = px;
    g_vpix[i * 3 + 1] = py;
    g_vpix[i * 3 + 2] = cz;
}

// ---------------------------------------------------------------------------
// K2: scatter rasterization. One block per (face, row-slice, batch).
// Key = (bits(d) << 32) | fid  -> atomicMin == (min d, then min fid),
// exactly the reference's chunked-scan tie-break semantics.
// ---------------------------------------------------------------------------
__global__ void raster_kernel(const int* __restrict__ vi) {
    int f = blockIdx.x;
    int slice = blockIdx.y;
    int n = blockIdx.z;

    int i0 = vi[f * 3 + 0];
    int i1 = vi[f * 3 + 1];
    int i2 = vi[f * 3 + 2];
    const float* p0 = g_vpix + ((size_t)n * NV + i0) * 3;
    const float* p1 = g_vpix + ((size_t)n * NV + i1) * 3;
    const float* p2 = g_vpix + ((size_t)n * NV + i2) * 3;
    float x0 = p0[0], y0 = p0[1], z0 = p0[2];
    float x1 = p1[0], y1 = p1[1], z1 = p1[2];
    float x2 = p2[0], y2 = p2[1], z2 = p2[2];

    // Same area formula as reference _bary
    float area = (x1 - x0) * (y2 - y0) - (y1 - y0) * (x2 - x0);
    if (!(fabsf(area) > 1e-9f)) return;           // degenerate -> never inside
    float inv = 1.0f / area;
    float rz0 = 1.0f / z0, rz1 = 1.0f / z1, rz2 = 1.0f / z2;

    float minx = fminf(x0, fminf(x1, x2));
    float maxx = fmaxf(x0, fmaxf(x1, x2));
    float miny = fminf(y0, fminf(y1, y2));
    float maxy = fmaxf(y0, fmaxf(y1, y2));
    if (!(minx <= maxx) || !(miny <= maxy)) return;  // NaN guard

    // inside (b>=0 all) => point in convex hull => in bbox; pad 1px for rounding
    int xs = max(0, (int)ceilf(minx - 0.5f) - 1);
    int xe = min(IMW - 1, (int)floorf(maxx - 0.5f) + 1);
    int ys = max(0, (int)ceilf(miny - 0.5f) - 1);
    int ye = min(IMH - 1, (int)floorf(maxy - 0.5f) + 1);
    if (xs > xe || ys > ye) return;

    float dx21 = x2 - x1, dy21 = y2 - y1;
    float dx02 = x0 - x2, dy02 = y0 - y2;
    float dx10 = x1 - x0, dy10 = y1 - y0;

    unsigned long long fid = (unsigned long long)(unsigned)f;

    for (int iy = ys + slice; iy <= ye; iy += RSLICE) {
        float py = (float)iy + 0.5f;
        float t0y = dx21 * (py - y1);
        float t1y = dx02 * (py - y2);
        float t2y = dx10 * (py - y0);
        unsigned long long* rowp = g_zkey + ((size_t)n * IMH + iy) * IMW;
        for (int ix = xs + (int)threadIdx.x; ix <= xe; ix += (int)blockDim.x) {
            float px = (float)ix + 0.5f;
            float b0 = (t0y - dy21 * (px - x1)) * inv;
            float b1 = (t1y - dy02 * (px - x2)) * inv;
            float b2 = (t2y - dy10 * (px - x0)) * inv;
            if (b0 >= 0.0f && b1 >= 0.0f && b2 >= 0.0f) {
                float zinv = b0 * rz0 + b1 * rz1 + b2 * rz2;
                if (zinv > EPSF) {
                    float d = 1.0f / zinv;   // IEEE div: exact ref tie semantics
                    unsigned long long key =
                        ((unsigned long long)__float_as_uint(d) << 32) | fid;
                    if (key < __ldcg(rowp + ix)) {
                        atomicMin(rowp + ix, key);
                    }
                }
            }
        }
    }
}

// ---------------------------------------------------------------------------
// K3: per-pixel render: bary -> uv interp -> bilinear texture sample -> out
// ---------------------------------------------------------------------------
__global__ void render_kernel(const float* __restrict__ tex,
                              const float* __restrict__ vt,
                              const int* __restrict__ vi,
                              const int* __restrict__ vti,
                              float* __restrict__ out) {
    int i = blockIdx.x * blockDim.x + threadIdx.x;
    if (i >= NB * IMH * IMW) return;
    int n = i / (IMH * IMW);
    int pix = i % (IMH * IMW);
    int iy = pix / IMW;
    int ix = pix % IMW;

    unsigned long long key = g_zkey[i];
    float outc[3] = {0.0f, 0.0f, 0.0f};

    if (key != ZKEY_INIT) {
        int f = (int)(unsigned)(key & 0xffffffffu);
        int i0 = vi[f * 3 + 0], i1 = vi[f * 3 + 1], i2 = vi[f * 3 + 2];
        const float* p0 = g_vpix + ((size_t)n * NV + i0) * 3;
        const float* p1 = g_vpix + ((size_t)n * NV + i1) * 3;
        const float* p2 = g_vpix + ((size_t)n * NV + i2) * 3;
        float x0 = p0[0], y0 = p0[1], z0 = p0[2];
        float x1 = p1[0], y1 = p1[1], z1 = p1[2];
        float x2 = p2[0], y2 = p2[1], z2 = p2[2];

        float px = (float)ix + 0.5f;
        float py = (float)iy + 0.5f;

        float area = (x1 - x0) * (y2 - y0) - (y1 - y0) * (x2 - x0);
        bool ok = fabsf(area) > 1e-9f;
        float inv = 1.0f / (ok ? area : 1.0f);
        float b0 = ((x2 - x1) * (py - y1) - (y2 - y1) * (px - x1)) * inv;
        float b1 = ((x0 - x2) * (py - y2) - (y0 - y2) * (px - x2)) * inv;
        float b2 = ((x1 - x0) * (py - y0) - (y1 - y0) * (px - x0)) * inv;

        float w0 = b0 / z0;
        float w1 = b1 / z1;
        float w2 = b2 / z2;
        float zinv = fmaxf(w0 + w1 + w2, EPSF);
        float bb0 = w0 / zinv;
        float bb1 = w1 / zinv;
        float bb2 = w2 / zinv;

        int t0 = vti[f * 3 + 0], t1 = vti[f * 3 + 1], t2 = vti[f * 3 + 2];
        float u0 = 2.0f * vt[t0 * 2 + 0] - 1.0f, v0 = 2.0f * vt[t0 * 2 + 1] - 1.0f;
        float u1 = 2.0f * vt[t1 * 2 + 0] - 1.0f, v1 = 2.0f * vt[t1 * 2 + 1] - 1.0f;
        float u2 = 2.0f * vt[t2 * 2 + 0] - 1.0f, v2 = 2.0f * vt[t2 * 2 + 1] - 1.0f;

        float gx = u0 * bb0 + u1 * bb1 + u2 * bb2;
        float gy = v0 * bb0 + v1 * bb1 + v2 * bb2;

        float fx = ((gx + 1.0f) * (float)TW - 1.0f) * 0.5f;
        float fy = ((gy + 1.0f) * (float)TH - 1.0f) * 0.5f;
        float fx0 = floorf(fx);
        float fy0 = floorf(fy);
        float wx = fx - fx0;
        float wy = fy - fy0;
        int x0i = min(max((int)fx0, 0), TW - 1);
        int x1i = min(max((int)fx0 + 1, 0), TW - 1);
        int y0i = min(max((int)fy0, 0), TH - 1);
        int y1i = min(max((int)fy0 + 1, 0), TH - 1);

        const float* texn = tex + (size_t)n * 3 * TH * TW;
#pragma unroll
        for (int c = 0; c < 3; c++) {
            const float* base = texn + (size_t)c * TH * TW;
            float t00 = base[y0i * TW + x0i];
            float t01 = base[y0i * TW + x1i];
            float t10 = base[y1i * TW + x0i];
            float t11 = base[y1i * TW + x1i];
            // reference op order: ((a + b) + c) + d with left-assoc weights
            float val = t00 * (1.0f - wx) * (1.0f - wy)
                      + t01 * wx * (1.0f - wy)
                      + t10 * (1.0f - wx) * wy
                      + t11 * wx * wy;
            outc[c] = val;
        }
    }

#pragma unroll
    for (int c = 0; c < 3; c++) {
        out[((size_t)n * 3 + c) * (IMH * IMW) + pix] = outc[c];
    }
}

// ---------------------------------------------------------------------------
extern "C" void kernel_launch(void* const* d_in, const int* in_sizes, int n_in,
                              void* d_out, int out_size) {
    const float* v       = (const float*)d_in[0];
    const float* tex     = (const float*)d_in[1];
    const float* campos  = (const float*)d_in[2];
    const float* camrot  = (const float*)d_in[3];
    const float* focal   = (const float*)d_in[4];
    const float* princpt = (const float*)d_in[5];
    const float* vt      = (const float*)d_in[6];
    const int*   vi      = (const int*)d_in[7];
    const int*   vti     = (const int*)d_in[8];
    float* out = (float*)d_out;

    init_kernel<<<(NB * IMH * IMW + 255) / 256, 256>>>();
    vtx_kernel<<<(NB * NV + 127) / 128, 128>>>(v, campos, camrot, focal, princpt);
    raster_kernel<<<dim3(NF, RSLICE, NB), 128>>>(vi);
    render_kernel<<<(NB * IMH * IMW + 127) / 128, 128>>>(tex, vt, vi, vti, out);
}